// round 7
// baseline (speedup 1.0000x reference)
#include <cuda_runtime.h>
#include <cuda_bf16.h>
#include <cstdint>

// Problem dims (fixed by reference)
#define B_   2
#define S_   2048
#define D_   1024
#define E_   1024
#define H_   16
#define HD_  64
#define MTOT (B_*S_)        // 4096
#define NQKV (3*E_)         // 3072
#define BHN  (B_*H_)        // 32

// ---- static device scratch (no allocations allowed) ----
__device__ __align__(256) float g_q[(size_t)BHN * S_ * HD_];       // tf32-rounded
__device__ __align__(256) float g_k[(size_t)BHN * S_ * HD_];
__device__ __align__(256) float g_v[(size_t)BHN * S_ * HD_];
__device__ __align__(256) float g_vals[(size_t)MTOT * E_];         // tf32-rounded O
__device__ __align__(256) float g_x_r[(size_t)MTOT * D_];          // tf32-rounded x
__device__ __align__(256) float g_wqkv_r[(size_t)NQKV * D_];       // tf32-rounded w_qkv
__device__ __align__(256) float g_wout_r[(size_t)D_ * E_];         // tf32-rounded w_out
__device__ __align__(256) float g_out_scratch[(size_t)MTOT * D_];
__device__ __align__(256) float g_attn_scratch[(size_t)BHN * S_ * S_];

__device__ __forceinline__ uint32_t f2tf32(float x) {
    uint32_t u;
    asm("cvt.rna.tf32.f32 %0, %1;" : "=r"(u) : "f"(x));
    return u;
}

__device__ __forceinline__ void mma_tf32(float c[4], const uint32_t a[4], const uint32_t b[2]) {
    asm volatile(
        "mma.sync.aligned.m16n8k8.row.col.f32.tf32.tf32.f32 "
        "{%0,%1,%2,%3}, {%4,%5,%6,%7}, {%8,%9}, {%0,%1,%2,%3};\n"
        : "+f"(c[0]), "+f"(c[1]), "+f"(c[2]), "+f"(c[3])
        : "r"(a[0]), "r"(a[1]), "r"(a[2]), "r"(a[3]), "r"(b[0]), "r"(b[1]));
}

__device__ __forceinline__ void cpa16(void* s, const void* g) {
    uint32_t sa = (uint32_t)__cvta_generic_to_shared(s);
    asm volatile("cp.async.cg.shared.global [%0], [%1], 16;" :: "r"(sa), "l"(g));
}
#define CP_COMMIT asm volatile("cp.async.commit_group;")
#define CP_WAIT0  asm volatile("cp.async.wait_group 0;")
#define CP_WAIT2  asm volatile("cp.async.wait_group 2;")

__device__ __forceinline__ void stg_cs_v2(float* p, float a, float b) {
    asm volatile("st.global.cs.v2.f32 [%0], {%1,%2};" :: "l"(p), "f"(a), "f"(b));
}

// ============================================================================
// Pre-round fp32 arrays to tf32 (cvt.rna) in gmem, so GEMMs can cp.async raw.
// ============================================================================
__global__ void round_kernel(const float* __restrict__ in, float* __restrict__ out, int n) {
    int i = (blockIdx.x * blockDim.x + threadIdx.x) * 4;
    if (i < n) {
        float4 v = *reinterpret_cast<const float4*>(in + i);
        v.x = __uint_as_float(f2tf32(v.x));
        v.y = __uint_as_float(f2tf32(v.y));
        v.z = __uint_as_float(f2tf32(v.z));
        v.w = __uint_as_float(f2tf32(v.w));
        *reinterpret_cast<float4*>(out + i) = v;
    }
}

// ============================================================================
// Dense GEMMs, tf32 mma.sync. Pre-rounded operands -> raw cp.async, 4-stage
// pipeline, scalar-LDS fragments (20-word stride, conflict-free).
// MODE 0: qkv — A=g_x_r[4096,1024], B=g_wqkv_r[3072,1024]; +bias, scatter q/k/v
// MODE 3: proj — A=g_vals[4096,1024], B=g_wout_r[1024,1024]; +bias -> out
// ============================================================================
#define GSTAGES 4
#define GSAS 20
#define GEMM_SMEM (GSTAGES * 2 * 128 * GSAS * 4)   // 81920 B

template<int MODE>
__global__ __launch_bounds__(256)
void mma_gemm(const float* __restrict__ bias, float* __restrict__ pC) {
    constexpr int BM = 128, BN = 128, BK = 16;
    constexpr int KDIM = 1024;
    constexpr int KT = KDIM / BK;

    extern __shared__ uint32_t smg[];

    const int tid = threadIdx.x;
    const int wid = tid >> 5, lane = tid & 31;
    const int g = lane >> 2, tg = lane & 3;
    const int warpM = wid / 4, warpN = wid % 4;
    const int bm = blockIdx.y * BM;
    const int bn = blockIdx.x * BN;

    const float* gA = (MODE == 0) ? g_x_r : g_vals;
    const float* gB = (MODE == 0) ? g_wqkv_r : g_wout_r;

    const int lrow = tid >> 2, lc4 = (tid & 3) * 4;

    auto issue_stage = [&](int kt, int s) {
        uint32_t* As = smg + (size_t)s * 2 * 128 * GSAS;
        uint32_t* Bs = As + 128 * GSAS;
        #pragma unroll
        for (int rep = 0; rep < 2; rep++) {
            int row = rep * 64 + lrow;
            cpa16(&As[row * GSAS + lc4], gA + (size_t)(bm + row) * KDIM + kt * BK + lc4);
            cpa16(&Bs[row * GSAS + lc4], gB + (size_t)(bn + row) * KDIM + kt * BK + lc4);
        }
        CP_COMMIT;
    };

    #pragma unroll
    for (int s = 0; s < GSTAGES - 1; s++) issue_stage(s, s);

    float acc[4][4][4] = {};

    #pragma unroll 1
    for (int kt = 0; kt < KT; kt++) {
        CP_WAIT2;
        __syncthreads();

        const uint32_t* As = smg + (size_t)(kt % GSTAGES) * 2 * 128 * GSAS;
        const uint32_t* Bs = As + 128 * GSAS;

        #pragma unroll
        for (int ks = 0; ks < 2; ks++) {
            const int kb = ks * 8;
            uint32_t af[4][4], bfr[4][2];
            #pragma unroll
            for (int i = 0; i < 4; i++) {
                const int rm = warpM * 64 + i * 16;
                af[i][0] = As[(rm + g) * GSAS + kb + tg];
                af[i][1] = As[(rm + g + 8) * GSAS + kb + tg];
                af[i][2] = As[(rm + g) * GSAS + kb + tg + 4];
                af[i][3] = As[(rm + g + 8) * GSAS + kb + tg + 4];
            }
            #pragma unroll
            for (int j = 0; j < 4; j++) {
                const int cn = warpN * 32 + j * 8;
                bfr[j][0] = Bs[(cn + g) * GSAS + kb + tg];
                bfr[j][1] = Bs[(cn + g) * GSAS + kb + tg + 4];
            }
            #pragma unroll
            for (int i = 0; i < 4; i++)
                #pragma unroll
                for (int j = 0; j < 4; j++)
                    mma_tf32(acc[i][j], af[i], bfr[j]);
        }

        if (kt + GSTAGES - 1 < KT) issue_stage(kt + GSTAGES - 1, (kt + GSTAGES - 1) % GSTAGES);
    }

    #pragma unroll
    for (int i = 0; i < 4; i++) {
        const int rm = bm + warpM * 64 + i * 16;
        const int r0 = rm + g, r1 = rm + g + 8;
        #pragma unroll
        for (int j = 0; j < 4; j++) {
            const int n0 = bn + warpN * 32 + j * 8;
            const int nc = n0 + 2 * tg;
            float c0 = acc[i][j][0], c1 = acc[i][j][1];
            float c2 = acc[i][j][2], c3 = acc[i][j][3];
            if (MODE == 0) {
                const float b0 = bias[nc], b1 = bias[nc + 1];
                const int h = n0 / (3 * HD_);
                const int which = (n0 % (3 * HD_)) / HD_;
                const int d = (n0 % HD_) + 2 * tg;
                float* dst = (which == 0) ? g_q : (which == 1) ? g_k : g_v;
                const int bb0 = r0 >> 11, ss0 = r0 & (S_ - 1);
                const int bb1 = r1 >> 11, ss1 = r1 & (S_ - 1);
                float2 v0 = make_float2(__uint_as_float(f2tf32(c0 + b0)), __uint_as_float(f2tf32(c1 + b1)));
                float2 v1 = make_float2(__uint_as_float(f2tf32(c2 + b0)), __uint_as_float(f2tf32(c3 + b1)));
                *reinterpret_cast<float2*>(dst + ((((size_t)bb0 * H_ + h) * S_ + ss0) * HD_ + d)) = v0;
                *reinterpret_cast<float2*>(dst + ((((size_t)bb1 * H_ + h) * S_ + ss1) * HD_ + d)) = v1;
            } else {
                float* outp = pC ? pC : g_out_scratch;
                const float b0 = bias[nc], b1 = bias[nc + 1];
                *reinterpret_cast<float2*>(outp + (size_t)r0 * D_ + nc) = make_float2(c0 + b0, c1 + b1);
                *reinterpret_cast<float2*>(outp + (size_t)r1 * D_ + nc) = make_float2(c2 + b0, c3 + b1);
            }
        }
    }
}

// ============================================================================
// Fused attention, 64-row K/V tiles for 2 CTAs/SM.
// Block = (128 q-rows, one bh), 256 threads / 8 warps (2x4 warp grid).
// Pass 1: l[row] = sum exp(q.k/64); Pass 2: recompute S, write attn, O += P@V.
// Smem: Qs[128][68], Xs[2][64][76], Ps[128][68], Lrow -> ~106.5 KB.
// ============================================================================
#define QSTR 68
#define XSTR 76
#define PSTR 68
#define KTILE 64
#define NKT (S_ / KTILE)   // 32
#define FA_SMEM ((128*QSTR + 2*KTILE*XSTR + 128*PSTR) * 4 + 512)

__global__ __launch_bounds__(256)
void fused_attn(float* __restrict__ attn_ext) {
    extern __shared__ uint32_t sm[];
    uint32_t* Qs = sm;                          // 128*68
    uint32_t* Xs = Qs + 128 * QSTR;             // 2 * 64*76
    uint32_t* Ps = Xs + 2 * KTILE * XSTR;       // 128*68
    float* Lrow  = (float*)(Ps + 128 * PSTR);   // 128

    const int tid = threadIdx.x;
    const int wid = tid >> 5, lane = tid & 31;
    const int g = lane >> 2, tg = lane & 3;
    const int warpM = wid >> 2, warpN = wid & 3;   // 2x4
    const int wm = warpM * 64;
    const int bm = blockIdx.x * 128;
    const int bh = blockIdx.y;
    const float sc = 1.0f / (float)HD_;

    const float* gQ = g_q + (size_t)bh * S_ * HD_ + (size_t)bm * HD_;
    const float* gK = g_k + (size_t)bh * S_ * HD_;
    const float* gV = g_v + (size_t)bh * S_ * HD_;
    float* attnp = (attn_ext ? attn_ext : g_attn_scratch) + (size_t)bh * S_ * S_;

    auto load_q = [&]() {
        #pragma unroll
        for (int rep = 0; rep < 8; rep++) {
            int idx = rep * 256 + tid, row = idx >> 4, q4 = idx & 15;
            cpa16(&Qs[row * QSTR + q4 * 4], gQ + row * HD_ + q4 * 4);
        }
    };
    // 64 rows x 64 cols tile
    auto load_kv = [&](const float* src, int kt, int b) {
        const float* base = src + (size_t)kt * KTILE * HD_;
        #pragma unroll
        for (int rep = 0; rep < 4; rep++) {
            int idx = rep * 256 + tid, row = idx >> 4, q4 = idx & 15;
            cpa16(&Xs[b * KTILE * XSTR + row * XSTR + q4 * 4], base + row * HD_ + q4 * 4);
        }
    };

    // S = Q @ K^T (128x64), K tile in Xs[b]; warp tile 64x16 -> acc[4][2][4]
    auto compute_S = [&](int b, float acc[4][2][4]) {
        #pragma unroll
        for (int i = 0; i < 4; i++)
            #pragma unroll
            for (int j = 0; j < 2; j++)
                #pragma unroll
                for (int e = 0; e < 4; e++) acc[i][j][e] = 0.0f;
        const uint32_t* Kb = Xs + b * KTILE * XSTR;
        #pragma unroll
        for (int ks = 0; ks < 8; ks++) {
            const int kb = ks * 8;
            uint32_t af[4][4], bfr[2][2];
            #pragma unroll
            for (int i = 0; i < 4; i++) {
                const int r = wm + i * 16 + g;
                af[i][0] = Qs[r * QSTR + kb + tg];
                af[i][1] = Qs[(r + 8) * QSTR + kb + tg];
                af[i][2] = Qs[r * QSTR + kb + tg + 4];
                af[i][3] = Qs[(r + 8) * QSTR + kb + tg + 4];
            }
            #pragma unroll
            for (int j = 0; j < 2; j++) {
                const int c = warpN * 16 + j * 8 + g;
                bfr[j][0] = Kb[c * XSTR + kb + tg];
                bfr[j][1] = Kb[c * XSTR + kb + tg + 4];
            }
            #pragma unroll
            for (int i = 0; i < 4; i++)
                #pragma unroll
                for (int j = 0; j < 2; j++)
                    mma_tf32(acc[i][j], af[i], bfr[j]);
        }
    };

    // ---- prologue ----
    if (tid < 128) Lrow[tid] = 0.0f;
    load_q();
    load_kv(gK, 0, 0);
    CP_COMMIT;
    CP_WAIT0;
    __syncthreads();

    // ================= pass 1: row sums of exp =================
    float lp[4][2] = {};
    int a = 0;
    #pragma unroll 1
    for (int kt = 0; kt < NKT; kt++) {
        if (kt < NKT - 1) { load_kv(gK, kt + 1, a ^ 1); CP_COMMIT; }
        float acc[4][2][4];
        compute_S(a, acc);
        #pragma unroll
        for (int i = 0; i < 4; i++)
            #pragma unroll
            for (int j = 0; j < 2; j++) {
                lp[i][0] += __expf(acc[i][j][0] * sc) + __expf(acc[i][j][1] * sc);
                lp[i][1] += __expf(acc[i][j][2] * sc) + __expf(acc[i][j][3] * sc);
            }
        if (kt < NKT - 1) { CP_WAIT0; __syncthreads(); a ^= 1; }
    }
    #pragma unroll
    for (int i = 0; i < 4; i++)
        #pragma unroll
        for (int h = 0; h < 2; h++) {
            float v = lp[i][h];
            v += __shfl_xor_sync(0xffffffff, v, 1);
            v += __shfl_xor_sync(0xffffffff, v, 2);
            if (tg == 0) atomicAdd(&Lrow[wm + i * 16 + h * 8 + g], v);
        }
    __syncthreads();
    if (tid < 128) Lrow[tid] = 1.0f / Lrow[tid];

    // reload K[0] for pass 2
    load_kv(gK, 0, a ^ 1);
    CP_COMMIT;
    CP_WAIT0;
    a ^= 1;
    __syncthreads();

    // ================= pass 2: attn write + O accumulation =================
    float oacc[4][2][4] = {};
    #pragma unroll 1
    for (int kt = 0; kt < NKT; kt++) {
        if (kt < NKT - 1) { load_kv(gK, kt + 1, a ^ 1); CP_COMMIT; }
        float acc[4][2][4];
        compute_S(a, acc);
        __syncthreads();                       // all warps done reading K in Xs[a]
        load_kv(gV, kt, a); CP_COMMIT;         // V[kt] overwrites K[kt]

        #pragma unroll
        for (int i = 0; i < 4; i++) {
            const int r0 = wm + i * 16 + g, r1 = r0 + 8;
            const float li0 = Lrow[r0], li1 = Lrow[r1];
            #pragma unroll
            for (int j = 0; j < 2; j++) {
                const int col = warpN * 16 + j * 8 + 2 * tg;
                float p0 = __expf(acc[i][j][0] * sc) * li0;
                float p1 = __expf(acc[i][j][1] * sc) * li0;
                float p2 = __expf(acc[i][j][2] * sc) * li1;
                float p3 = __expf(acc[i][j][3] * sc) * li1;
                stg_cs_v2(attnp + (size_t)(bm + r0) * S_ + kt * KTILE + col, p0, p1);
                stg_cs_v2(attnp + (size_t)(bm + r1) * S_ + kt * KTILE + col, p2, p3);
                Ps[r0 * PSTR + col]     = f2tf32(p0);
                Ps[r0 * PSTR + col + 1] = f2tf32(p1);
                Ps[r1 * PSTR + col]     = f2tf32(p2);
                Ps[r1 * PSTR + col + 1] = f2tf32(p3);
            }
        }
        CP_WAIT0;
        __syncthreads();   // Ps + V visible

        // O += P @ V  (P: [128m][64k] in Ps; V: [64k][64n] in Xs[a])
        const uint32_t* Vb = Xs + a * KTILE * XSTR;
        #pragma unroll
        for (int k8 = 0; k8 < 8; k8++) {
            const int kb = k8 * 8;
            uint32_t af[4][4], bfr[2][2];
            #pragma unroll
            for (int i = 0; i < 4; i++) {
                const int r = wm + i * 16 + g;
                af[i][0] = Ps[r * PSTR + kb + tg];
                af[i][1] = Ps[(r + 8) * PSTR + kb + tg];
                af[i][2] = Ps[r * PSTR + kb + tg + 4];
                af[i][3] = Ps[(r + 8) * PSTR + kb + tg + 4];
            }
            #pragma unroll
            for (int j = 0; j < 2; j++) {
                const int cn = warpN * 16 + j * 8 + g;
                bfr[j][0] = Vb[(kb + tg) * XSTR + cn];
                bfr[j][1] = Vb[(kb + tg + 4) * XSTR + cn];
            }
            #pragma unroll
            for (int i = 0; i < 4; i++)
                #pragma unroll
                for (int j = 0; j < 2; j++)
                    mma_tf32(oacc[i][j], af[i], bfr[j]);
        }
        if (kt < NKT - 1) {
            __syncthreads();   // PV done reading Xs[a] before next K load reuses it
            a ^= 1;
        }
    }

    // ---- epilogue: O -> g_vals, tf32-rounded so proj can cp.async raw ----
    const int bb = bh >> 4, h = bh & 15;
    float* vbase = g_vals + (size_t)bb * S_ * E_ + (size_t)h * HD_;
    #pragma unroll
    for (int i = 0; i < 4; i++) {
        const int r0 = bm + wm + i * 16 + g, r1 = r0 + 8;
        #pragma unroll
        for (int j = 0; j < 2; j++) {
            const int cn = warpN * 16 + j * 8 + 2 * tg;
            *reinterpret_cast<float2*>(vbase + (size_t)r0 * E_ + cn) =
                make_float2(__uint_as_float(f2tf32(oacc[i][j][0])), __uint_as_float(f2tf32(oacc[i][j][1])));
            *reinterpret_cast<float2*>(vbase + (size_t)r1 * E_ + cn) =
                make_float2(__uint_as_float(f2tf32(oacc[i][j][2])), __uint_as_float(f2tf32(oacc[i][j][3])));
        }
    }
}

// ============================================================================
// Launch. Inputs: x, w_qkv, b_qkv, w_out, b_out.
// ============================================================================
extern "C" void kernel_launch(void* const* d_in, const int* in_sizes, int n_in,
                              void* d_out, int out_size) {
    const float* x     = (const float*)d_in[0];
    const float* w_qkv = (const float*)d_in[1];
    const float* b_qkv = (const float*)d_in[2];
    const float* w_out = (const float*)d_in[3];
    const float* b_out = (const float*)d_in[4];
    float* dout = (float*)d_out;

    const long long OUTN  = (long long)MTOT * D_;
    const long long ATTNN = (long long)BHN * S_ * S_;
    float* out_ext  = nullptr;
    float* attn_ext = nullptr;
    const long long osz = (long long)out_size;
    if (osz >= OUTN + ATTNN) { out_ext = dout; attn_ext = dout + OUTN; }
    else if (osz == ATTNN)   { attn_ext = dout; }
    else                     { out_ext = dout; }

    cudaFuncSetAttribute(fused_attn, cudaFuncAttributeMaxDynamicSharedMemorySize, FA_SMEM);
    cudaFuncSetAttribute(mma_gemm<0>, cudaFuncAttributeMaxDynamicSharedMemorySize, GEMM_SMEM);
    cudaFuncSetAttribute(mma_gemm<3>, cudaFuncAttributeMaxDynamicSharedMemorySize, GEMM_SMEM);

    float* xr; float* wqr; float* wor;
    cudaGetSymbolAddress((void**)&xr,  g_x_r);
    cudaGetSymbolAddress((void**)&wqr, g_wqkv_r);
    cudaGetSymbolAddress((void**)&wor, g_wout_r);

    dim3 t(256);
    round_kernel<<<(MTOT * D_ / 4 + 255) / 256, 256>>>(x, xr, MTOT * D_);
    round_kernel<<<(NQKV * D_ / 4 + 255) / 256, 256>>>(w_qkv, wqr, NQKV * D_);
    round_kernel<<<(D_ * E_ / 4 + 255) / 256, 256>>>(w_out, wor, D_ * E_);

    mma_gemm<0><<<dim3(NQKV / 128, MTOT / 128), t, GEMM_SMEM>>>(b_qkv, nullptr);
    fused_attn<<<dim3(S_ / 128, BHN), t, FA_SMEM>>>(attn_ext);
    mma_gemm<3><<<dim3(D_ / 128, MTOT / 128), t, GEMM_SMEM>>>(b_out, out_ext);
}

// round 8
// speedup vs baseline: 1.6695x; 1.6695x over previous
#include <cuda_runtime.h>
#include <cuda_fp16.h>
#include <cstdint>

// Problem dims (fixed by reference)
#define B_   2
#define S_   2048
#define D_   1024
#define E_   1024
#define H_   16
#define HD_  64
#define MTOT (B_*S_)        // 4096
#define NQKV (3*E_)         // 3072
#define BHN  (B_*H_)        // 32

// ---- static device scratch (no allocations allowed) ----
__device__ __align__(256) __half g_q[(size_t)BHN * S_ * HD_];     // [bh][s][d]
__device__ __align__(256) __half g_k[(size_t)BHN * S_ * HD_];     // [bh][s][d]
__device__ __align__(256) __half g_vt[(size_t)BHN * HD_ * S_];    // [bh][d][s]  (transposed!)
__device__ __align__(256) __half g_vals[(size_t)MTOT * E_];       // O, fp16
__device__ __align__(256) __half g_x_h[(size_t)MTOT * D_];
__device__ __align__(256) __half g_wqkv_h[(size_t)NQKV * D_];
__device__ __align__(256) __half g_wout_h[(size_t)D_ * E_];
__device__ __align__(256) float  g_out_scratch[(size_t)MTOT * D_];
__device__ __align__(256) float  g_attn_scratch[(size_t)BHN * S_ * S_];

__device__ __forceinline__ uint32_t h2u(__half2 h) { return *reinterpret_cast<uint32_t*>(&h); }

__device__ __forceinline__ void mma_f16(float c[4], const uint32_t a[4], const uint32_t b[2]) {
    asm volatile(
        "mma.sync.aligned.m16n8k16.row.col.f32.f16.f16.f32 "
        "{%0,%1,%2,%3}, {%4,%5,%6,%7}, {%8,%9}, {%0,%1,%2,%3};\n"
        : "+f"(c[0]), "+f"(c[1]), "+f"(c[2]), "+f"(c[3])
        : "r"(a[0]), "r"(a[1]), "r"(a[2]), "r"(a[3]), "r"(b[0]), "r"(b[1]));
}

__device__ __forceinline__ void cpa16(void* s, const void* g) {
    uint32_t sa = (uint32_t)__cvta_generic_to_shared(s);
    asm volatile("cp.async.cg.shared.global [%0], [%1], 16;" :: "r"(sa), "l"(g));
}
#define CP_COMMIT asm volatile("cp.async.commit_group;")
#define CP_WAIT0  asm volatile("cp.async.wait_group 0;")
#define CP_WAIT2  asm volatile("cp.async.wait_group 2;")

__device__ __forceinline__ void stg_cs_v2(float* p, float a, float b) {
    asm volatile("st.global.cs.v2.f32 [%0], {%1,%2};" :: "l"(p), "f"(a), "f"(b));
}

// ============================================================================
// fp32 -> fp16 conversion (8 elems/thread)
// ============================================================================
__global__ void cvt_half(const float* __restrict__ in, __half* __restrict__ out, int n) {
    int i = (blockIdx.x * blockDim.x + threadIdx.x) * 8;
    if (i < n) {
        float4 a = *reinterpret_cast<const float4*>(in + i);
        float4 b = *reinterpret_cast<const float4*>(in + i + 4);
        uint4 u;
        u.x = h2u(__floats2half2_rn(a.x, a.y));
        u.y = h2u(__floats2half2_rn(a.z, a.w));
        u.z = h2u(__floats2half2_rn(b.x, b.y));
        u.w = h2u(__floats2half2_rn(b.z, b.w));
        *reinterpret_cast<uint4*>(out + i) = u;
    }
}

// ============================================================================
// Dense GEMMs, fp16 mma m16n8k16, fp32 accum. 4-stage cp.async pipeline.
// Word (u32) = fp16 pair along K; fragment addressing identical to tf32-k8.
// MODE 0: qkv — A=g_x_h, B=g_wqkv_h; +bias, scatter q/k (row-major) + v (transposed)
// MODE 3: proj — A=g_vals, B=g_wout_h; +bias -> out (fp32)
// ============================================================================
#define GSTAGES 4
#define GSAS 20                                 // 16 pair-words + 4 pad
#define GEMM_SMEM (GSTAGES * 2 * 128 * GSAS * 4)

template<int MODE>
__global__ __launch_bounds__(256)
void mma_gemm(const float* __restrict__ bias, float* __restrict__ pC) {
    constexpr int BM = 128, BN = 128;
    constexpr int KDIM = 1024;                  // fp16 elements
    constexpr int KT = KDIM / 32;               // 32 stages of 32 k

    extern __shared__ uint32_t smg[];

    const int tid = threadIdx.x;
    const int wid = tid >> 5, lane = tid & 31;
    const int g = lane >> 2, tg = lane & 3;
    const int warpM = wid / 4, warpN = wid % 4; // warp tile 64x32
    const int bm = blockIdx.y * BM;
    const int bn = blockIdx.x * BN;

    const __half* gA = (MODE == 0) ? g_x_h : g_vals;
    const __half* gB = (MODE == 0) ? g_wqkv_h : g_wout_h;

    const int lrow = tid >> 2, lch = tid & 3;   // 4 x 16B chunks per 64B row

    auto issue_stage = [&](int kt, int s) {
        uint32_t* As = smg + (size_t)s * 2 * 128 * GSAS;
        uint32_t* Bs = As + 128 * GSAS;
        #pragma unroll
        for (int rep = 0; rep < 2; rep++) {
            int row = rep * 64 + lrow;
            cpa16(&As[row * GSAS + lch * 4], gA + (size_t)(bm + row) * KDIM + kt * 32 + lch * 8);
            cpa16(&Bs[row * GSAS + lch * 4], gB + (size_t)(bn + row) * KDIM + kt * 32 + lch * 8);
        }
        CP_COMMIT;
    };

    #pragma unroll
    for (int s = 0; s < GSTAGES - 1; s++) issue_stage(s, s);

    float acc[4][4][4] = {};

    #pragma unroll 1
    for (int kt = 0; kt < KT; kt++) {
        if (kt < KT - 2) { CP_WAIT2; } else { CP_WAIT0; }   // tail: wait all (race fix)
        __syncthreads();

        const uint32_t* As = smg + (size_t)(kt % GSTAGES) * 2 * 128 * GSAS;
        const uint32_t* Bs = As + 128 * GSAS;

        #pragma unroll
        for (int ks = 0; ks < 2; ks++) {        // two k16 steps per stage
            const int kb = ks * 8;
            uint32_t af[4][4], bfr[4][2];
            #pragma unroll
            for (int i = 0; i < 4; i++) {
                const int rm = warpM * 64 + i * 16;
                af[i][0] = As[(rm + g) * GSAS + kb + tg];
                af[i][1] = As[(rm + g + 8) * GSAS + kb + tg];
                af[i][2] = As[(rm + g) * GSAS + kb + tg + 4];
                af[i][3] = As[(rm + g + 8) * GSAS + kb + tg + 4];
            }
            #pragma unroll
            for (int j = 0; j < 4; j++) {
                const int cn = warpN * 32 + j * 8;
                bfr[j][0] = Bs[(cn + g) * GSAS + kb + tg];
                bfr[j][1] = Bs[(cn + g) * GSAS + kb + tg + 4];
            }
            #pragma unroll
            for (int i = 0; i < 4; i++)
                #pragma unroll
                for (int j = 0; j < 4; j++)
                    mma_f16(acc[i][j], af[i], bfr[j]);
        }

        if (kt + GSTAGES - 1 < KT) issue_stage(kt + GSTAGES - 1, (kt + GSTAGES - 1) % GSTAGES);
    }

    #pragma unroll
    for (int i = 0; i < 4; i++) {
        const int rm = bm + warpM * 64 + i * 16;
        const int r0 = rm + g, r1 = rm + g + 8;
        #pragma unroll
        for (int j = 0; j < 4; j++) {
            const int n0 = bn + warpN * 32 + j * 8;
            const int nc = n0 + 2 * tg;
            float c0 = acc[i][j][0], c1 = acc[i][j][1];
            float c2 = acc[i][j][2], c3 = acc[i][j][3];
            if (MODE == 0) {
                const float b0 = bias[nc], b1 = bias[nc + 1];
                const int h = n0 / (3 * HD_);
                const int which = (n0 % (3 * HD_)) / HD_;
                const int d = (n0 % HD_) + 2 * tg;
                const int bb = r0 >> 11;                    // r1 same block (see note)
                const int ss0 = r0 & (S_ - 1), ss1 = r1 & (S_ - 1);
                if (which < 2) {
                    __half* dst = (which == 0) ? g_q : g_k;
                    size_t base = (((size_t)bb * H_ + h) * S_) * HD_ + d;
                    *reinterpret_cast<__half2*>(dst + base + (size_t)ss0 * HD_) = __floats2half2_rn(c0 + b0, c1 + b1);
                    *reinterpret_cast<__half2*>(dst + base + (size_t)ss1 * HD_) = __floats2half2_rn(c2 + b0, c3 + b1);
                } else {
                    size_t base = ((size_t)bb * H_ + h) * HD_;
                    g_vt[(base + d) * S_ + ss0]     = __float2half_rn(c0 + b0);
                    g_vt[(base + d + 1) * S_ + ss0] = __float2half_rn(c1 + b1);
                    g_vt[(base + d) * S_ + ss1]     = __float2half_rn(c2 + b0);
                    g_vt[(base + d + 1) * S_ + ss1] = __float2half_rn(c3 + b1);
                }
            } else {
                float* outp = pC ? pC : g_out_scratch;
                const float b0 = bias[nc], b1 = bias[nc + 1];
                *reinterpret_cast<float2*>(outp + (size_t)r0 * D_ + nc) = make_float2(c0 + b0, c1 + b1);
                *reinterpret_cast<float2*>(outp + (size_t)r1 * D_ + nc) = make_float2(c2 + b0, c3 + b1);
            }
        }
    }
}

// ============================================================================
// Fused attention, fp16 mma. Block = (128 q-rows, one bh), 8 warps (2x4).
// Pass 1: l = sum exp(q.k/64); pass 2: recompute S, write attn fp32, O += P@V.
// Smem (~90.6 KB): Qs[128][36], Xs[2][4608] (K 128x36 / Vt 64x68), Ps[128][68].
// ============================================================================
#define QSTR 36
#define KSTR 36
#define VSTR 68
#define PSTR 68
#define XBUF 4608
#define NKT (S_ / 128)   // 16
#define FA_SMEM ((128*QSTR + 2*XBUF + 128*PSTR) * 4 + 512)

__global__ __launch_bounds__(256)
void fused_attn(float* __restrict__ attn_ext) {
    extern __shared__ uint32_t sm[];
    uint32_t* Qs = sm;                          // 128*36
    uint32_t* Xs = Qs + 128 * QSTR;             // 2 * 4608
    uint32_t* Ps = Xs + 2 * XBUF;               // 128*68
    float* Lrow  = (float*)(Ps + 128 * PSTR);   // 128

    const int tid = threadIdx.x;
    const int wid = tid >> 5, lane = tid & 31;
    const int g = lane >> 2, tg = lane & 3;
    const int warpM = wid >> 2, warpN = wid & 3;   // 2x4
    const int wm = warpM * 64;
    const int bm = blockIdx.x * 128;
    const int bh = blockIdx.y;
    const float sc = 1.0f / (float)HD_;

    const __half* gQ  = g_q  + (size_t)bh * S_ * HD_ + (size_t)bm * HD_;
    const __half* gK  = g_k  + (size_t)bh * S_ * HD_;
    const __half* gVt = g_vt + (size_t)bh * HD_ * S_;
    float* attnp = (attn_ext ? attn_ext : g_attn_scratch) + (size_t)bh * S_ * S_;

    // Q/K tiles: 128 rows x 64 fp16 (128B = 8 chunks)
    auto load_q = [&]() {
        #pragma unroll
        for (int rep = 0; rep < 4; rep++) {
            int idx = rep * 256 + tid, row = idx >> 3, ch = idx & 7;
            cpa16(&Qs[row * QSTR + ch * 4], gQ + (size_t)row * HD_ + ch * 8);
        }
    };
    auto load_k = [&](int kt, int b) {
        const __half* base = gK + (size_t)kt * 128 * HD_;
        #pragma unroll
        for (int rep = 0; rep < 4; rep++) {
            int idx = rep * 256 + tid, row = idx >> 3, ch = idx & 7;
            cpa16(&Xs[b * XBUF + row * KSTR + ch * 4], base + (size_t)row * HD_ + ch * 8);
        }
    };
    // V^T tile: 64 rows (d) x 128 fp16 (s) = 256B = 16 chunks
    auto load_v = [&](int kt, int b) {
        const __half* base = gVt + (size_t)kt * 128;
        #pragma unroll
        for (int rep = 0; rep < 4; rep++) {
            int idx = rep * 256 + tid, row = idx >> 4, ch = idx & 15;
            cpa16(&Xs[b * XBUF + row * VSTR + ch * 4], base + (size_t)row * S_ + ch * 8);
        }
    };

    // S = Q @ K^T (128x128), K tile in Xs[b]; 4 k16 steps over HD=64
    auto compute_S = [&](int b, float acc[4][4][4]) {
        #pragma unroll
        for (int i = 0; i < 4; i++)
            #pragma unroll
            for (int j = 0; j < 4; j++)
                #pragma unroll
                for (int e = 0; e < 4; e++) acc[i][j][e] = 0.0f;
        const uint32_t* Kb = Xs + b * XBUF;
        #pragma unroll
        for (int ks = 0; ks < 4; ks++) {
            const int kb = ks * 8;
            uint32_t af[4][4], bfr[4][2];
            #pragma unroll
            for (int i = 0; i < 4; i++) {
                const int r = wm + i * 16 + g;
                af[i][0] = Qs[r * QSTR + kb + tg];
                af[i][1] = Qs[(r + 8) * QSTR + kb + tg];
                af[i][2] = Qs[r * QSTR + kb + tg + 4];
                af[i][3] = Qs[(r + 8) * QSTR + kb + tg + 4];
            }
            #pragma unroll
            for (int j = 0; j < 4; j++) {
                const int c = warpN * 32 + j * 8 + g;
                bfr[j][0] = Kb[c * KSTR + kb + tg];
                bfr[j][1] = Kb[c * KSTR + kb + tg + 4];
            }
            #pragma unroll
            for (int i = 0; i < 4; i++)
                #pragma unroll
                for (int j = 0; j < 4; j++)
                    mma_f16(acc[i][j], af[i], bfr[j]);
        }
    };

    // ---- prologue ----
    if (tid < 128) Lrow[tid] = 0.0f;
    load_q();
    load_k(0, 0);
    CP_COMMIT;
    CP_WAIT0;
    __syncthreads();

    // ================= pass 1: row sums of exp =================
    float lp[4][2] = {};
    int a = 0;
    #pragma unroll 1
    for (int kt = 0; kt < NKT; kt++) {
        if (kt < NKT - 1) { load_k(kt + 1, a ^ 1); CP_COMMIT; }
        float acc[4][4][4];
        compute_S(a, acc);
        #pragma unroll
        for (int i = 0; i < 4; i++)
            #pragma unroll
            for (int j = 0; j < 4; j++) {
                lp[i][0] += __expf(acc[i][j][0] * sc) + __expf(acc[i][j][1] * sc);
                lp[i][1] += __expf(acc[i][j][2] * sc) + __expf(acc[i][j][3] * sc);
            }
        if (kt < NKT - 1) { CP_WAIT0; __syncthreads(); a ^= 1; }
    }
    #pragma unroll
    for (int i = 0; i < 4; i++)
        #pragma unroll
        for (int h = 0; h < 2; h++) {
            float v = lp[i][h];
            v += __shfl_xor_sync(0xffffffff, v, 1);
            v += __shfl_xor_sync(0xffffffff, v, 2);
            if (tg == 0) atomicAdd(&Lrow[wm + i * 16 + h * 8 + g], v);
        }
    __syncthreads();
    if (tid < 128) Lrow[tid] = 1.0f / Lrow[tid];

    // reload K[0] for pass 2
    load_k(0, a ^ 1);
    CP_COMMIT;
    CP_WAIT0;
    a ^= 1;
    __syncthreads();

    // ================= pass 2: attn write + O accumulation =================
    float oacc[4][2][4] = {};
    #pragma unroll 1
    for (int kt = 0; kt < NKT; kt++) {
        if (kt < NKT - 1) { load_k(kt + 1, a ^ 1); CP_COMMIT; }
        float acc[4][4][4];
        compute_S(a, acc);
        __syncthreads();                   // all warps done reading K in Xs[a]
        load_v(kt, a); CP_COMMIT;          // V^T[kt] overwrites K[kt]

        #pragma unroll
        for (int i = 0; i < 4; i++) {
            const int r0 = wm + i * 16 + g, r1 = r0 + 8;
            const float li0 = Lrow[r0], li1 = Lrow[r1];
            #pragma unroll
            for (int j = 0; j < 4; j++) {
                const int col = warpN * 32 + j * 8 + 2 * tg;   // even
                float p0 = __expf(acc[i][j][0] * sc) * li0;
                float p1 = __expf(acc[i][j][1] * sc) * li0;
                float p2 = __expf(acc[i][j][2] * sc) * li1;
                float p3 = __expf(acc[i][j][3] * sc) * li1;
                stg_cs_v2(attnp + (size_t)(bm + r0) * S_ + kt * 128 + col, p0, p1);
                stg_cs_v2(attnp + (size_t)(bm + r1) * S_ + kt * 128 + col, p2, p3);
                Ps[r0 * PSTR + (col >> 1)] = h2u(__floats2half2_rn(p0, p1));
                Ps[r1 * PSTR + (col >> 1)] = h2u(__floats2half2_rn(p2, p3));
            }
        }
        CP_WAIT0;
        __syncthreads();   // Ps + V visible

        // O += P @ V  (P [128m][128k] fp16 pairs; V^T [64n][128k] pairs)
        const uint32_t* Vb = Xs + a * XBUF;
        #pragma unroll
        for (int k8 = 0; k8 < 8; k8++) {
            const int kb = k8 * 8;
            uint32_t af[4][4], bfr[2][2];
            #pragma unroll
            for (int i = 0; i < 4; i++) {
                const int r = wm + i * 16 + g;
                af[i][0] = Ps[r * PSTR + kb + tg];
                af[i][1] = Ps[(r + 8) * PSTR + kb + tg];
                af[i][2] = Ps[r * PSTR + kb + tg + 4];
                af[i][3] = Ps[(r + 8) * PSTR + kb + tg + 4];
            }
            #pragma unroll
            for (int j = 0; j < 2; j++) {
                const int cn = warpN * 16 + j * 8 + g;         // d index
                bfr[j][0] = Vb[cn * VSTR + kb + tg];
                bfr[j][1] = Vb[cn * VSTR + kb + tg + 4];
            }
            #pragma unroll
            for (int i = 0; i < 4; i++)
                #pragma unroll
                for (int j = 0; j < 2; j++)
                    mma_f16(oacc[i][j], af[i], bfr[j]);
        }
        if (kt < NKT - 1) {
            __syncthreads();   // PV done reading Xs[a] before next K load reuses it
            a ^= 1;
        }
    }

    // ---- epilogue: O (128x64) -> g_vals fp16 [b*S+s][h*64+d] ----
    const int bb = bh >> 4, h = bh & 15;
    __half* vbase = g_vals + (size_t)bb * S_ * E_ + (size_t)h * HD_;
    #pragma unroll
    for (int i = 0; i < 4; i++) {
        const int r0 = bm + wm + i * 16 + g, r1 = r0 + 8;
        #pragma unroll
        for (int j = 0; j < 2; j++) {
            const int cn = warpN * 16 + j * 8 + 2 * tg;
            *reinterpret_cast<__half2*>(vbase + (size_t)r0 * E_ + cn) =
                __floats2half2_rn(oacc[i][j][0], oacc[i][j][1]);
            *reinterpret_cast<__half2*>(vbase + (size_t)r1 * E_ + cn) =
                __floats2half2_rn(oacc[i][j][2], oacc[i][j][3]);
        }
    }
}

// ============================================================================
// Launch. Inputs: x, w_qkv, b_qkv, w_out, b_out.
// ============================================================================
extern "C" void kernel_launch(void* const* d_in, const int* in_sizes, int n_in,
                              void* d_out, int out_size) {
    const float* x     = (const float*)d_in[0];
    const float* w_qkv = (const float*)d_in[1];
    const float* b_qkv = (const float*)d_in[2];
    const float* w_out = (const float*)d_in[3];
    const float* b_out = (const float*)d_in[4];
    float* dout = (float*)d_out;

    const long long OUTN  = (long long)MTOT * D_;
    const long long ATTNN = (long long)BHN * S_ * S_;
    float* out_ext  = nullptr;
    float* attn_ext = nullptr;
    const long long osz = (long long)out_size;
    if (osz >= OUTN + ATTNN) { out_ext = dout; attn_ext = dout + OUTN; }
    else if (osz == ATTNN)   { attn_ext = dout; }
    else                     { out_ext = dout; }

    cudaFuncSetAttribute(fused_attn, cudaFuncAttributeMaxDynamicSharedMemorySize, FA_SMEM);
    cudaFuncSetAttribute(mma_gemm<0>, cudaFuncAttributeMaxDynamicSharedMemorySize, GEMM_SMEM);
    cudaFuncSetAttribute(mma_gemm<3>, cudaFuncAttributeMaxDynamicSharedMemorySize, GEMM_SMEM);

    __half* xh; __half* wqh; __half* woh;
    cudaGetSymbolAddress((void**)&xh,  g_x_h);
    cudaGetSymbolAddress((void**)&wqh, g_wqkv_h);
    cudaGetSymbolAddress((void**)&woh, g_wout_h);

    dim3 t(256);
    cvt_half<<<(MTOT * D_ / 8 + 255) / 256, 256>>>(x, xh, MTOT * D_);
    cvt_half<<<(NQKV * D_ / 8 + 255) / 256, 256>>>(w_qkv, wqh, NQKV * D_);
    cvt_half<<<(D_ * E_ / 8 + 255) / 256, 256>>>(w_out, woh, D_ * E_);

    mma_gemm<0><<<dim3(NQKV / 128, MTOT / 128), t, GEMM_SMEM>>>(b_qkv, nullptr);
    fused_attn<<<dim3(S_ / 128, BHN), t, FA_SMEM>>>(attn_ext);
    mma_gemm<3><<<dim3(D_ / 128, MTOT / 128), t, GEMM_SMEM>>>(b_out, out_ext);
}

// round 9
// speedup vs baseline: 1.7248x; 1.0331x over previous
#include <cuda_runtime.h>
#include <cuda_fp16.h>
#include <cstdint>

// Problem dims (fixed by reference)
#define B_   2
#define S_   2048
#define D_   1024
#define E_   1024
#define H_   16
#define HD_  64
#define MTOT (B_*S_)        // 4096
#define NQKV (3*E_)         // 3072
#define BHN  (B_*H_)        // 32

// ---- static device scratch (no allocations allowed) ----
__device__ __align__(256) __half g_q[(size_t)BHN * S_ * HD_];     // [bh][s][d]
__device__ __align__(256) __half g_k[(size_t)BHN * S_ * HD_];     // [bh][s][d]
__device__ __align__(256) __half g_vt[(size_t)BHN * HD_ * S_];    // [bh][d][s]  (transposed)
__device__ __align__(256) __half g_vals[(size_t)MTOT * E_];       // O, fp16
__device__ __align__(256) __half g_x_h[(size_t)MTOT * D_];
__device__ __align__(256) __half g_wqkv_h[(size_t)NQKV * D_];
__device__ __align__(256) __half g_wout_h[(size_t)D_ * E_];
__device__ __align__(256) float  g_out_scratch[(size_t)MTOT * D_];
__device__ __align__(256) float  g_attn_scratch[(size_t)BHN * S_ * S_];

__device__ __forceinline__ uint32_t h2u(__half2 h) { return *reinterpret_cast<uint32_t*>(&h); }

__device__ __forceinline__ void mma_f16(float c[4], const uint32_t a[4], const uint32_t b[2]) {
    asm volatile(
        "mma.sync.aligned.m16n8k16.row.col.f32.f16.f16.f32 "
        "{%0,%1,%2,%3}, {%4,%5,%6,%7}, {%8,%9}, {%0,%1,%2,%3};\n"
        : "+f"(c[0]), "+f"(c[1]), "+f"(c[2]), "+f"(c[3])
        : "r"(a[0]), "r"(a[1]), "r"(a[2]), "r"(a[3]), "r"(b[0]), "r"(b[1]));
}

__device__ __forceinline__ void cpa16(void* s, const void* g) {
    uint32_t sa = (uint32_t)__cvta_generic_to_shared(s);
    asm volatile("cp.async.cg.shared.global [%0], [%1], 16;" :: "r"(sa), "l"(g));
}
#define CP_COMMIT asm volatile("cp.async.commit_group;")
#define CP_WAIT0  asm volatile("cp.async.wait_group 0;")
#define CP_WAIT2  asm volatile("cp.async.wait_group 2;")

__device__ __forceinline__ void stg_cs_v2(float* p, float a, float b) {
    asm volatile("st.global.cs.v2.f32 [%0], {%1,%2};" :: "l"(p), "f"(a), "f"(b));
}

// ============================================================================
// fp32 -> fp16 conversion (8 elems/thread)
// ============================================================================
__global__ void cvt_half(const float* __restrict__ in, __half* __restrict__ out, int n) {
    int i = (blockIdx.x * blockDim.x + threadIdx.x) * 8;
    if (i < n) {
        float4 a = *reinterpret_cast<const float4*>(in + i);
        float4 b = *reinterpret_cast<const float4*>(in + i + 4);
        uint4 u;
        u.x = h2u(__floats2half2_rn(a.x, a.y));
        u.y = h2u(__floats2half2_rn(a.z, a.w));
        u.z = h2u(__floats2half2_rn(b.x, b.y));
        u.w = h2u(__floats2half2_rn(b.z, b.w));
        *reinterpret_cast<uint4*>(out + i) = u;
    }
}

// ============================================================================
// Dense GEMMs, fp16 mma m16n8k16, fp32 accum. (unchanged from round 8)
// MODE 0: qkv — +bias, scatter q/k row-major + v transposed
// MODE 3: proj — +bias -> out (fp32)
// ============================================================================
#define GSTAGES 4
#define GSAS 20
#define GEMM_SMEM (GSTAGES * 2 * 128 * GSAS * 4)

template<int MODE>
__global__ __launch_bounds__(256)
void mma_gemm(const float* __restrict__ bias, float* __restrict__ pC) {
    constexpr int BM = 128, BN = 128;
    constexpr int KDIM = 1024;
    constexpr int KT = KDIM / 32;

    extern __shared__ uint32_t smg[];

    const int tid = threadIdx.x;
    const int wid = tid >> 5, lane = tid & 31;
    const int g = lane >> 2, tg = lane & 3;
    const int warpM = wid / 4, warpN = wid % 4;
    const int bm = blockIdx.y * BM;
    const int bn = blockIdx.x * BN;

    const __half* gA = (MODE == 0) ? g_x_h : g_vals;
    const __half* gB = (MODE == 0) ? g_wqkv_h : g_wout_h;

    const int lrow = tid >> 2, lch = tid & 3;

    auto issue_stage = [&](int kt, int s) {
        uint32_t* As = smg + (size_t)s * 2 * 128 * GSAS;
        uint32_t* Bs = As + 128 * GSAS;
        #pragma unroll
        for (int rep = 0; rep < 2; rep++) {
            int row = rep * 64 + lrow;
            cpa16(&As[row * GSAS + lch * 4], gA + (size_t)(bm + row) * KDIM + kt * 32 + lch * 8);
            cpa16(&Bs[row * GSAS + lch * 4], gB + (size_t)(bn + row) * KDIM + kt * 32 + lch * 8);
        }
        CP_COMMIT;
    };

    #pragma unroll
    for (int s = 0; s < GSTAGES - 1; s++) issue_stage(s, s);

    float acc[4][4][4] = {};

    #pragma unroll 1
    for (int kt = 0; kt < KT; kt++) {
        if (kt < KT - 2) { CP_WAIT2; } else { CP_WAIT0; }
        __syncthreads();

        const uint32_t* As = smg + (size_t)(kt % GSTAGES) * 2 * 128 * GSAS;
        const uint32_t* Bs = As + 128 * GSAS;

        #pragma unroll
        for (int ks = 0; ks < 2; ks++) {
            const int kb = ks * 8;
            uint32_t af[4][4], bfr[4][2];
            #pragma unroll
            for (int i = 0; i < 4; i++) {
                const int rm = warpM * 64 + i * 16;
                af[i][0] = As[(rm + g) * GSAS + kb + tg];
                af[i][1] = As[(rm + g + 8) * GSAS + kb + tg];
                af[i][2] = As[(rm + g) * GSAS + kb + tg + 4];
                af[i][3] = As[(rm + g + 8) * GSAS + kb + tg + 4];
            }
            #pragma unroll
            for (int j = 0; j < 4; j++) {
                const int cn = warpN * 32 + j * 8;
                bfr[j][0] = Bs[(cn + g) * GSAS + kb + tg];
                bfr[j][1] = Bs[(cn + g) * GSAS + kb + tg + 4];
            }
            #pragma unroll
            for (int i = 0; i < 4; i++)
                #pragma unroll
                for (int j = 0; j < 4; j++)
                    mma_f16(acc[i][j], af[i], bfr[j]);
        }

        if (kt + GSTAGES - 1 < KT) issue_stage(kt + GSTAGES - 1, (kt + GSTAGES - 1) % GSTAGES);
    }

    #pragma unroll
    for (int i = 0; i < 4; i++) {
        const int rm = bm + warpM * 64 + i * 16;
        const int r0 = rm + g, r1 = rm + g + 8;
        #pragma unroll
        for (int j = 0; j < 4; j++) {
            const int n0 = bn + warpN * 32 + j * 8;
            const int nc = n0 + 2 * tg;
            float c0 = acc[i][j][0], c1 = acc[i][j][1];
            float c2 = acc[i][j][2], c3 = acc[i][j][3];
            if (MODE == 0) {
                const float b0 = bias[nc], b1 = bias[nc + 1];
                const int h = n0 / (3 * HD_);
                const int which = (n0 % (3 * HD_)) / HD_;
                const int d = (n0 % HD_) + 2 * tg;
                const int bb = r0 >> 11;
                const int ss0 = r0 & (S_ - 1), ss1 = r1 & (S_ - 1);
                if (which < 2) {
                    __half* dst = (which == 0) ? g_q : g_k;
                    size_t base = (((size_t)bb * H_ + h) * S_) * HD_ + d;
                    *reinterpret_cast<__half2*>(dst + base + (size_t)ss0 * HD_) = __floats2half2_rn(c0 + b0, c1 + b1);
                    *reinterpret_cast<__half2*>(dst + base + (size_t)ss1 * HD_) = __floats2half2_rn(c2 + b0, c3 + b1);
                } else {
                    size_t base = ((size_t)bb * H_ + h) * HD_;
                    g_vt[(base + d) * S_ + ss0]     = __float2half_rn(c0 + b0);
                    g_vt[(base + d + 1) * S_ + ss0] = __float2half_rn(c1 + b1);
                    g_vt[(base + d) * S_ + ss1]     = __float2half_rn(c2 + b0);
                    g_vt[(base + d + 1) * S_ + ss1] = __float2half_rn(c3 + b1);
                }
            } else {
                float* outp = pC ? pC : g_out_scratch;
                const float b0 = bias[nc], b1 = bias[nc + 1];
                *reinterpret_cast<float2*>(outp + (size_t)r0 * D_ + nc) = make_float2(c0 + b0, c1 + b1);
                *reinterpret_cast<float2*>(outp + (size_t)r1 * D_ + nc) = make_float2(c2 + b0, c3 + b1);
            }
        }
    }
}

// ============================================================================
// Fused attention, FA2-style: warp tile = 16 q-rows x full 128 k-cols.
// S accumulators convert IN REGISTERS to PV A-fragments (no P smem trip).
// Row sums are per-warp register reductions (no atomics/smem).
// K and V have independent double buffers -> one __syncthreads per tile.
// ============================================================================
#define QSTR 36
#define KSTR 36
#define VSTR 68
#define NKT (S_ / 128)                     // 16
#define KS_OFF (128 * QSTR)
#define VS_OFF (KS_OFF + 2 * 128 * KSTR)
#define FA_SMEM ((128*QSTR + 2*128*KSTR + 2*64*VSTR) * 4)   // 90112 B

__global__ __launch_bounds__(256)
void fused_attn(float* __restrict__ attn_ext) {
    extern __shared__ uint32_t sm[];
    uint32_t* Qs = sm;                     // 128 x 36
    uint32_t* Ks = sm + KS_OFF;            // 2 x 128 x 36
    uint32_t* Vs = sm + VS_OFF;            // 2 x 64 x 68

    const int tid = threadIdx.x;
    const int wid = tid >> 5, lane = tid & 31;
    const int g = lane >> 2, tg = lane & 3;
    const int wm = wid * 16;               // warp's 16 q-rows
    const int bm = blockIdx.x * 128;
    const int bh = blockIdx.y;
    const float sc = 1.0f / (float)HD_;

    const __half* gQ  = g_q  + (size_t)bh * S_ * HD_ + (size_t)bm * HD_;
    const __half* gK  = g_k  + (size_t)bh * S_ * HD_;
    const __half* gVt = g_vt + (size_t)bh * HD_ * S_;
    float* attnp = (attn_ext ? attn_ext : g_attn_scratch) + (size_t)bh * S_ * S_;

    auto load_q = [&]() {
        #pragma unroll
        for (int rep = 0; rep < 4; rep++) {
            int idx = rep * 256 + tid, row = idx >> 3, ch = idx & 7;
            cpa16(&Qs[row * QSTR + ch * 4], gQ + (size_t)row * HD_ + ch * 8);
        }
    };
    auto load_k = [&](int kt, int b) {
        const __half* base = gK + (size_t)kt * 128 * HD_;
        #pragma unroll
        for (int rep = 0; rep < 4; rep++) {
            int idx = rep * 256 + tid, row = idx >> 3, ch = idx & 7;
            cpa16(&Ks[b * 128 * KSTR + row * KSTR + ch * 4], base + (size_t)row * HD_ + ch * 8);
        }
    };
    auto load_v = [&](int kt, int b) {   // V^T tile: 64 d-rows x 128 s-cols
        const __half* base = gVt + (size_t)kt * 128;
        #pragma unroll
        for (int rep = 0; rep < 4; rep++) {
            int idx = rep * 256 + tid, row = idx >> 4, ch = idx & 15;
            cpa16(&Vs[b * 64 * VSTR + row * VSTR + ch * 4], base + (size_t)row * S_ + ch * 8);
        }
    };

    // S(16x128) = Q_warp @ K^T : one m16 A-frag, 16 n8 B-frags, 4 k16 steps
    auto compute_S = [&](const uint32_t* Kb, float sacc[16][4]) {
        #pragma unroll
        for (int j = 0; j < 16; j++)
            #pragma unroll
            for (int e = 0; e < 4; e++) sacc[j][e] = 0.0f;
        #pragma unroll
        for (int ks = 0; ks < 4; ks++) {
            const int kb = ks * 8;
            uint32_t af[4];
            af[0] = Qs[(wm + g) * QSTR + kb + tg];
            af[1] = Qs[(wm + g + 8) * QSTR + kb + tg];
            af[2] = Qs[(wm + g) * QSTR + kb + tg + 4];
            af[3] = Qs[(wm + g + 8) * QSTR + kb + tg + 4];
            #pragma unroll
            for (int j = 0; j < 16; j++) {
                uint32_t bf[2];
                bf[0] = Kb[(8 * j + g) * KSTR + kb + tg];
                bf[1] = Kb[(8 * j + g) * KSTR + kb + tg + 4];
                mma_f16(sacc[j], af, bf);
            }
        }
    };

    // ---- prologue ----
    load_q();
    load_k(0, 0);
    CP_COMMIT;
    CP_WAIT0;
    __syncthreads();

    // ================= pass 1: row sums of exp (registers only) ============
    float lp0 = 0.0f, lp1 = 0.0f;
    int b = 0;
    #pragma unroll 1
    for (int kt = 0; kt < NKT; kt++) {
        if (kt < NKT - 1) { load_k(kt + 1, b ^ 1); CP_COMMIT; }
        float sacc[16][4];
        compute_S(Ks + b * 128 * KSTR, sacc);
        #pragma unroll
        for (int j = 0; j < 16; j++) {
            lp0 += __expf(sacc[j][0] * sc) + __expf(sacc[j][1] * sc);
            lp1 += __expf(sacc[j][2] * sc) + __expf(sacc[j][3] * sc);
        }
        if (kt < NKT - 1) { CP_WAIT0; __syncthreads(); b ^= 1; }
    }
    lp0 += __shfl_xor_sync(0xffffffff, lp0, 1);
    lp0 += __shfl_xor_sync(0xffffffff, lp0, 2);
    lp1 += __shfl_xor_sync(0xffffffff, lp1, 1);
    lp1 += __shfl_xor_sync(0xffffffff, lp1, 2);
    const float li0 = 1.0f / lp0;          // row wm+g
    const float li1 = 1.0f / lp1;          // row wm+g+8

    // ================= pass 2: attn write + O accumulation =================
    load_k(0, 0); load_v(0, 0);
    CP_COMMIT;
    CP_WAIT0;
    __syncthreads();

    float oacc[8][4] = {};
    b = 0;
    #pragma unroll 1
    for (int kt = 0; kt < NKT; kt++) {
        if (kt < NKT - 1) { load_k(kt + 1, b ^ 1); load_v(kt + 1, b ^ 1); CP_COMMIT; }

        float sacc[16][4];
        compute_S(Ks + b * 128 * KSTR, sacc);

        // exp + normalize + attn write + pack PV A-fragments in registers
        uint32_t paf[8][4];
        float* arow0 = attnp + (size_t)(bm + wm + g) * S_ + kt * 128;
        float* arow1 = attnp + (size_t)(bm + wm + g + 8) * S_ + kt * 128;
        #pragma unroll
        for (int j = 0; j < 16; j++) {
            const int col = 8 * j + 2 * tg;
            float p0 = __expf(sacc[j][0] * sc) * li0;
            float p1 = __expf(sacc[j][1] * sc) * li0;
            float p2 = __expf(sacc[j][2] * sc) * li1;
            float p3 = __expf(sacc[j][3] * sc) * li1;
            stg_cs_v2(arow0 + col, p0, p1);
            stg_cs_v2(arow1 + col, p2, p3);
            paf[j >> 1][(j & 1) * 2 + 0] = h2u(__floats2half2_rn(p0, p1));
            paf[j >> 1][(j & 1) * 2 + 1] = h2u(__floats2half2_rn(p2, p3));
        }

        // O(16x64) += P(16x128) @ V(128x64);  V^T B-frags from smem
        const uint32_t* Vb = Vs + b * 64 * VSTR;
        #pragma unroll
        for (int ks = 0; ks < 8; ks++) {
            const int kb = ks * 8;
            #pragma unroll
            for (int jn = 0; jn < 8; jn++) {
                uint32_t bf[2];
                bf[0] = Vb[(8 * jn + g) * VSTR + kb + tg];
                bf[1] = Vb[(8 * jn + g) * VSTR + kb + tg + 4];
                mma_f16(oacc[jn], paf[ks], bf);
            }
        }

        if (kt < NKT - 1) { CP_WAIT0; __syncthreads(); b ^= 1; }
    }

    // ---- epilogue: O (16x64 per warp) -> g_vals fp16 [b*S+s][h*64+d] ----
    const int bb = bh >> 4, h = bh & 15;
    __half* vbase = g_vals + (size_t)bb * S_ * E_ + (size_t)h * HD_;
    const int r0 = bm + wm + g, r1 = r0 + 8;
    #pragma unroll
    for (int jn = 0; jn < 8; jn++) {
        const int cn = 8 * jn + 2 * tg;
        *reinterpret_cast<__half2*>(vbase + (size_t)r0 * E_ + cn) =
            __floats2half2_rn(oacc[jn][0], oacc[jn][1]);
        *reinterpret_cast<__half2*>(vbase + (size_t)r1 * E_ + cn) =
            __floats2half2_rn(oacc[jn][2], oacc[jn][3]);
    }
}

// ============================================================================
// Launch. Inputs: x, w_qkv, b_qkv, w_out, b_out.
// ============================================================================
extern "C" void kernel_launch(void* const* d_in, const int* in_sizes, int n_in,
                              void* d_out, int out_size) {
    const float* x     = (const float*)d_in[0];
    const float* w_qkv = (const float*)d_in[1];
    const float* b_qkv = (const float*)d_in[2];
    const float* w_out = (const float*)d_in[3];
    const float* b_out = (const float*)d_in[4];
    float* dout = (float*)d_out;

    const long long OUTN  = (long long)MTOT * D_;
    const long long ATTNN = (long long)BHN * S_ * S_;
    float* out_ext  = nullptr;
    float* attn_ext = nullptr;
    const long long osz = (long long)out_size;
    if (osz >= OUTN + ATTNN) { out_ext = dout; attn_ext = dout + OUTN; }
    else if (osz == ATTNN)   { attn_ext = dout; }
    else                     { out_ext = dout; }

    cudaFuncSetAttribute(fused_attn, cudaFuncAttributeMaxDynamicSharedMemorySize, FA_SMEM);
    cudaFuncSetAttribute(mma_gemm<0>, cudaFuncAttributeMaxDynamicSharedMemorySize, GEMM_SMEM);
    cudaFuncSetAttribute(mma_gemm<3>, cudaFuncAttributeMaxDynamicSharedMemorySize, GEMM_SMEM);

    __half* xh; __half* wqh; __half* woh;
    cudaGetSymbolAddress((void**)&xh,  g_x_h);
    cudaGetSymbolAddress((void**)&wqh, g_wqkv_h);
    cudaGetSymbolAddress((void**)&woh, g_wout_h);

    dim3 t(256);
    cvt_half<<<(MTOT * D_ / 8 + 255) / 256, 256>>>(x, xh, MTOT * D_);
    cvt_half<<<(NQKV * D_ / 8 + 255) / 256, 256>>>(w_qkv, wqh, NQKV * D_);
    cvt_half<<<(D_ * E_ / 8 + 255) / 256, 256>>>(w_out, woh, D_ * E_);

    mma_gemm<0><<<dim3(NQKV / 128, MTOT / 128), t, GEMM_SMEM>>>(b_qkv, nullptr);
    fused_attn<<<dim3(S_ / 128, BHN), t, FA_SMEM>>>(attn_ext);
    mma_gemm<3><<<dim3(D_ / 128, MTOT / 128), t, GEMM_SMEM>>>(b_out, out_ext);
}